// round 2
// baseline (speedup 1.0000x reference)
#include <cuda_runtime.h>
#include <math.h>

// RRN sudoku recurrent relational net.
// B=16, N=64 nodes, DEG=17, H=96, 32 steps.
// One kernel per step (warp-per-node), prologue precomputes xin/Xc, epilogue reduces loss/acc.

#define NSTEP 32

typedef unsigned long long ull;

// ---------- device scratch (allocation-free) ----------
__device__ float g_P[2][1024 * 96];      // edge-part of msg layer0, double buffered (cross-node gather)
__device__ float g_Q[1024 * 96];         // self-part + b0 (read-before-write within own warp)
__device__ float g_Ghh[1024 * 384];      // h @ W_hh
__device__ float g_Xc[1024 * 384];       // xin @ W_ih[96:] + b_ih + b_hh  (step-invariant)
__device__ float g_s[1024 * 96];         // LSTM cell state
__device__ float g_nodeloss[NSTEP * 1024];
__device__ int   g_nodeok[NSTEP * 1024];

// ---------- packed f32x2 helpers (Blackwell: 2 FMAs per instruction, PTX-only) ----------
__device__ __forceinline__ ull pack2(float x, float y) {
    ull r; asm("mov.b64 %0,{%1,%2};" : "=l"(r) : "f"(x), "f"(y)); return r;
}
__device__ __forceinline__ void unpack2(ull v, float& x, float& y) {
    asm("mov.b64 {%0,%1},%2;" : "=f"(x), "=f"(y) : "l"(v));
}
__device__ __forceinline__ void fma2(ull& d, ull a, ull b) {
    asm("fma.rn.f32x2 %0,%1,%2,%0;" : "+l"(d) : "l"(a), "l"(b));
}
__device__ __forceinline__ float sigf(float x) { return 1.f / (1.f + expf(-x)); }

// ---------- 18x96 @ 96x96 tile GEMM, Z kept transposed ZT[k][r] (stride 18), warp-private ----------
// Zout[c][r] = relu( sum_k Zin[k][r] * W[k][c] + b[c] )
__device__ __forceinline__ void gemm96(const float* Zin, float* Zout,
                                       const float* __restrict__ W,
                                       const float* __restrict__ bias, int lane)
{
#pragma unroll
    for (int pass = 0; pass < 3; pass++) {
        int c = lane + 32 * pass;
        ull acc[9];
#pragma unroll
        for (int p = 0; p < 9; p++) acc[p] = 0ull;
#pragma unroll 4
        for (int k = 0; k < 96; k++) {
            float wv = __ldg(W + k * 96 + c);
            ull w2 = pack2(wv, wv);
            const ull* zp = (const ull*)(Zin + k * 18);   // broadcast LDS.64 (same addr all lanes)
#pragma unroll
            for (int p = 0; p < 9; p++) fma2(acc[p], zp[p], w2);
        }
        float bv = __ldg(bias + c);
#pragma unroll
        for (int p = 0; p < 9; p++) {
            float x, y; unpack2(acc[p], x, y);
            x = fmaxf(x + bv, 0.f); y = fmaxf(y + bv, 0.f);
            *(ull*)(Zout + c * 18 + 2 * p) = pack2(x, y);
        }
    }
    __syncwarp();
}

// last message layer: no relu, sum over the 17 real rows (row 17 = pad, excluded)
__device__ __forceinline__ void gemm96_sum(const float* Zin, float* msg,
                                           const float* __restrict__ W,
                                           const float* __restrict__ bias, int lane)
{
#pragma unroll
    for (int pass = 0; pass < 3; pass++) {
        int c = lane + 32 * pass;
        ull acc[9];
#pragma unroll
        for (int p = 0; p < 9; p++) acc[p] = 0ull;
#pragma unroll 4
        for (int k = 0; k < 96; k++) {
            float wv = __ldg(W + k * 96 + c);
            ull w2 = pack2(wv, wv);
            const ull* zp = (const ull*)(Zin + k * 18);
#pragma unroll
            for (int p = 0; p < 9; p++) fma2(acc[p], zp[p], w2);
        }
        float bv = __ldg(bias + c);
        float s = 17.f * bv;
#pragma unroll
        for (int p = 0; p < 9; p++) {
            float x, y; unpack2(acc[p], x, y);
            s += x;
            if (p < 8) s += y;    // p==8 holds rows (16,17); row 17 is pad
        }
        msg[c] = s;
    }
    __syncwarp();
}

// ---------- main per-step kernel: warp == node ----------
__global__ void __launch_bounds__(128) step_kernel(
    int step,
    const int* __restrict__ edges, const int* __restrict__ target,
    const float* __restrict__ msg0_W, const float* __restrict__ msg0_b,
    const float* __restrict__ msg_Ws, const float* __restrict__ msg_bs,
    const float* __restrict__ W_ih, const float* __restrict__ W_hh,
    const float* __restrict__ pred_W, const float* __restrict__ pred_b,
    float* __restrict__ d_out)
{
    extern __shared__ float sm[];
    int tid = threadIdx.x, lane = tid & 31, w = tid >> 5;
    int n = blockIdx.x * 4 + w;
    int b = n >> 6, j = n & 63;

    float* ZTa    = sm + w * 1728;           // 96 x 18 transposed tile
    float* ZTb    = sm + 6912 + w * 1728;
    float* msg_s  = sm + 13824 + w * 96;
    float* gate_s = sm + 14208 + w * 384;
    float* h2_s   = sm + 15744 + w * 96;

    const float* Pin  = g_P[step & 1];
    float*       Pout = g_P[(step + 1) & 1];

    // ---- Z0: relu(P[edge] + Q[self]) into ZT layout ----
    {
        const float* Qn = g_Q + n * 96;
        for (int t = lane; t < 17 * 96; t += 32) {
            int r = t / 96, k = t - 96 * r;
            int e = b * 64 + __ldg(edges + j * 17 + r);
            float v = __ldg(Pin + e * 96 + k) + Qn[k];
            ZTa[k * 18 + r] = fmaxf(v, 0.f);
        }
        for (int k = lane; k < 96; k += 32) ZTa[k * 18 + 17] = 0.f;
    }
    __syncwarp();

    // ---- 3 message layers ----
    gemm96    (ZTa, ZTb,   msg_Ws,         msg_bs,       lane);
    gemm96    (ZTb, ZTa,   msg_Ws + 9216,  msg_bs + 96,  lane);
    gemm96_sum(ZTa, msg_s, msg_Ws + 18432, msg_bs + 192, lane);

    // ---- gates = msg @ W_ih[:96] + Xc + Ghh ----
#pragma unroll
    for (int q = 0; q < 6; q++) {
        int pi = lane + 32 * q;                 // column pair (2pi, 2pi+1)
        ull acc = 0ull;
#pragma unroll 4
        for (int k = 0; k < 96; k++) {
            ull w2 = __ldg((const ull*)(W_ih + k * 384 + 2 * pi));
            float mk = msg_s[k];
            fma2(acc, pack2(mk, mk), w2);
        }
        float x, y; unpack2(acc, x, y);
        const float* xc = g_Xc  + n * 384 + 2 * pi;
        const float* gh = g_Ghh + n * 384 + 2 * pi;
        gate_s[2 * pi]     = x + xc[0] + gh[0];
        gate_s[2 * pi + 1] = y + xc[1] + gh[1];
    }
    __syncwarp();

    // ---- LSTM ----
#pragma unroll
    for (int a = 0; a < 3; a++) {
        int d = lane + 32 * a;
        float gi = gate_s[d], gf = gate_s[96 + d], gg = gate_s[192 + d], go = gate_s[288 + d];
        float sp = g_s[n * 96 + d];
        float s2 = sigf(gf) * sp + sigf(gi) * tanhf(gg);
        float h2 = sigf(go) * tanhf(s2);
        g_s[n * 96 + d] = s2;
        h2_s[d] = h2;
    }
    __syncwarp();

    // ---- prediction head: logits, log-softmax, argmax (first max), loss ----
    if (lane < 8) {
        float logit = __ldg(pred_b + lane);
        for (int k = 0; k < 96; k++)
            logit = fmaf(h2_s[k], __ldg(pred_W + k * 8 + lane), logit);
        const unsigned msk = 0xFFu;
        float m = logit;
        for (int off = 4; off; off >>= 1) m = fmaxf(m, __shfl_xor_sync(msk, m, off));
        float se = expf(logit - m);
        for (int off = 4; off; off >>= 1) se += __shfl_xor_sync(msk, se, off);
        float lse = m + logf(se);
        float bl = logit; int bc = lane;
        for (int off = 4; off; off >>= 1) {
            float ol = __shfl_xor_sync(msk, bl, off);
            int   oc = __shfl_xor_sync(msk, bc, off);
            if (ol > bl || (ol == bl && oc < bc)) { bl = ol; bc = oc; }
        }
        int tgt = __ldg(target + n) - 1;
        if (lane == tgt) g_nodeloss[step * 1024 + n] = lse - logit;
        if (lane == 0) {
            g_nodeok[step * 1024 + n] = (bc == tgt) ? 1 : 0;
            if (step == NSTEP - 1) d_out[33 + n] = (float)bc;
        }
    }
    __syncwarp();

    if (step == NSTEP - 1) return;   // no next step

    // ---- P / Q / Ghh for the NEXT step, from this node's fresh h2 ----
    for (int jj = lane; jj < 48; jj += 32) {            // P = h2 @ msg0_W[:96]
        ull acc = 0ull;
#pragma unroll 4
        for (int k = 0; k < 96; k++) {
            ull w2 = __ldg((const ull*)(msg0_W + k * 96 + 2 * jj));
            float hk = h2_s[k];
            fma2(acc, pack2(hk, hk), w2);
        }
        *(ull*)(Pout + n * 96 + 2 * jj) = acc;
    }
    for (int jj = lane; jj < 48; jj += 32) {            // Q = h2 @ msg0_W[96:] + b0
        ull acc = 0ull;
#pragma unroll 4
        for (int k = 0; k < 96; k++) {
            ull w2 = __ldg((const ull*)(msg0_W + (96 + k) * 96 + 2 * jj));
            float hk = h2_s[k];
            fma2(acc, pack2(hk, hk), w2);
        }
        float x, y; unpack2(acc, x, y);
        x += __ldg(msg0_b + 2 * jj);
        y += __ldg(msg0_b + 2 * jj + 1);
        *(ull*)(g_Q + n * 96 + 2 * jj) = pack2(x, y);
    }
    for (int pi = lane; pi < 192; pi += 32) {           // Ghh = h2 @ W_hh
        ull acc = 0ull;
#pragma unroll 4
        for (int k = 0; k < 96; k++) {
            ull w2 = __ldg((const ull*)(W_hh + k * 384 + 2 * pi));
            float hk = h2_s[k];
            fma2(acc, pack2(hk, hk), w2);
        }
        *(ull*)(g_Ghh + n * 384 + 2 * pi) = acc;
    }
}

// ---------- prologue: feat -> xin MLP -> Xc; init P/Q/Ghh/s ----------
__global__ void __launch_bounds__(128) prologue_kernel(
    const int* __restrict__ x,
    const float* __restrict__ digit_emb, const float* __restrict__ row_emb,
    const float* __restrict__ col_emb,
    const float* __restrict__ in0_W, const float* __restrict__ in0_b,
    const float* __restrict__ in_Ws, const float* __restrict__ in_bs,
    const float* __restrict__ W_ih, const float* __restrict__ b_ih,
    const float* __restrict__ b_hh, const float* __restrict__ msg0_b)
{
    __shared__ float feat[4][48], va[4][96], vb[4][96];
    int tid = threadIdx.x, lane = tid & 31, w = tid >> 5;
    int n = blockIdx.x * 4 + w;
    int j = n & 63;

    if (lane < 16) {
        int xv = x[n];
        feat[w][lane]      = digit_emb[xv * 16 + lane];
        feat[w][16 + lane] = row_emb[(j >> 3) * 16 + lane];
        feat[w][32 + lane] = col_emb[(j & 7) * 16 + lane];
    }
    __syncwarp();

#pragma unroll
    for (int a = 0; a < 3; a++) {                       // layer0: 48 -> 96, relu
        int c = lane + 32 * a;
        float acc = in0_b[c];
        for (int k = 0; k < 48; k++) acc = fmaf(feat[w][k], in0_W[k * 96 + c], acc);
        va[w][c] = fmaxf(acc, 0.f);
    }
    __syncwarp();

    for (int l = 0; l < 3; l++) {                       // 3x 96->96 (relu on first two)
        const float* Wl = in_Ws + l * 9216;
        const float* bl = in_bs + l * 96;
        float* src = (l == 1) ? vb[w] : va[w];
        float* dst = (l == 1) ? va[w] : vb[w];
#pragma unroll
        for (int a = 0; a < 3; a++) {
            int c = lane + 32 * a;
            float acc = bl[c];
            for (int k = 0; k < 96; k++) acc = fmaf(src[k], Wl[k * 96 + c], acc);
            dst[c] = (l < 2) ? fmaxf(acc, 0.f) : acc;
        }
        __syncwarp();
    }
    // xin now in vb[w]

    for (int pi = lane; pi < 192; pi += 32) {           // Xc = xin @ W_ih[96:] + b_ih + b_hh
        ull acc = 0ull;
#pragma unroll 4
        for (int k = 0; k < 96; k++) {
            ull w2 = __ldg((const ull*)(W_ih + (96 + k) * 384 + 2 * pi));
            float xk = vb[w][k];
            fma2(acc, pack2(xk, xk), w2);
        }
        float xx, yy; unpack2(acc, xx, yy);
        g_Xc[n * 384 + 2 * pi]     = xx + b_ih[2 * pi]     + b_hh[2 * pi];
        g_Xc[n * 384 + 2 * pi + 1] = yy + b_ih[2 * pi + 1] + b_hh[2 * pi + 1];
    }

    // h0 = 0  =>  P=0, Q=b0, Ghh=0, s=0
    for (int t = lane; t < 96; t += 32) {
        g_P[0][n * 96 + t] = 0.f;
        g_Q[n * 96 + t]    = msg0_b[t];
        g_s[n * 96 + t]    = 0.f;
    }
    for (int t = lane; t < 384; t += 32) g_Ghh[n * 384 + t] = 0.f;
}

// ---------- epilogue: reduce loss + per-step accuracy ----------
__global__ void __launch_bounds__(512) epilogue_kernel(float* __restrict__ d_out)
{
    __shared__ int   cnt[32];
    __shared__ float red[512];
    int tid = threadIdx.x;
    if (tid < 32) cnt[tid] = 0;
    __syncthreads();

    int s = tid >> 4, b = tid & 15;                     // 32 steps x 16 batches
    int ok = 1;
    for (int jj = 0; jj < 64; jj++) ok &= g_nodeok[s * 1024 + b * 64 + jj];
    atomicAdd(&cnt[s], ok);

    float ls = 0.f;
    for (int i = tid; i < NSTEP * 1024; i += 512) ls += g_nodeloss[i];
    red[tid] = ls;
    __syncthreads();
    for (int off = 256; off; off >>= 1) {
        if (tid < off) red[tid] += red[tid + off];
        __syncthreads();
    }
    if (tid == 0)  d_out[0] = red[0] / (1024.f * 32.f);
    if (tid < 32)  d_out[1 + tid] = cnt[tid] * (1.f / 16.f);
}

// ---------- launch ----------
extern "C" void kernel_launch(void* const* d_in, const int* in_sizes, int n_in,
                              void* d_out, int out_size)
{
    (void)in_sizes; (void)n_in; (void)out_size;
    const int*   x         = (const int*)  d_in[0];
    const int*   target    = (const int*)  d_in[1];
    const int*   edges     = (const int*)  d_in[2];
    const float* digit_emb = (const float*)d_in[3];
    const float* row_emb   = (const float*)d_in[4];
    const float* col_emb   = (const float*)d_in[5];
    const float* in0_W     = (const float*)d_in[6];
    const float* in0_b     = (const float*)d_in[7];
    const float* in_Ws     = (const float*)d_in[8];
    const float* in_bs     = (const float*)d_in[9];
    const float* msg0_W    = (const float*)d_in[10];
    const float* msg0_b    = (const float*)d_in[11];
    const float* msg_Ws    = (const float*)d_in[12];
    const float* msg_bs    = (const float*)d_in[13];
    const float* W_ih      = (const float*)d_in[14];
    const float* W_hh      = (const float*)d_in[15];
    const float* b_ih      = (const float*)d_in[16];
    const float* b_hh      = (const float*)d_in[17];
    const float* pred_W    = (const float*)d_in[18];
    const float* pred_b    = (const float*)d_in[19];
    float* out = (float*)d_out;

    const int SMEM = 16128 * 4;   // 64512 B
    cudaFuncSetAttribute(step_kernel, cudaFuncAttributeMaxDynamicSharedMemorySize, SMEM);

    prologue_kernel<<<256, 128>>>(x, digit_emb, row_emb, col_emb,
                                  in0_W, in0_b, in_Ws, in_bs,
                                  W_ih, b_ih, b_hh, msg0_b);
    for (int s = 0; s < NSTEP; s++)
        step_kernel<<<256, 128, SMEM>>>(s, edges, target,
                                        msg0_W, msg0_b, msg_Ws, msg_bs,
                                        W_ih, W_hh, pred_W, pred_b, out);
    epilogue_kernel<<<1, 512>>>(out);
}

// round 3
// speedup vs baseline: 2.5991x; 2.5991x over previous
#include <cuda_runtime.h>
#include <math.h>

// RRN sudoku recurrent relational net. B=16, N=64, DEG=17, H=96, 32 steps.
// Round 2: CTA = 1 node x 3 warps (96 threads), grid=1024. Latency-hiding fixes.

#define NSTEP 32

typedef unsigned long long ull;

// ---------- device scratch (allocation-free) ----------
__device__ float g_P[2][1024 * 96];      // edge-part of msg layer0, double buffered
__device__ float g_Q[1024 * 96];         // self-part + b0
__device__ float g_Ghh[1024 * 384];      // h @ W_hh
__device__ float g_Xc[1024 * 384];       // xin @ W_ih[96:] + b_ih + b_hh (step-invariant)
__device__ float g_s[1024 * 96];         // LSTM cell state
__device__ float g_nodeloss[NSTEP * 1024];
__device__ int   g_nodeok[NSTEP * 1024];

// ---------- packed f32x2 helpers ----------
__device__ __forceinline__ ull pack2(float x, float y) {
    ull r; asm("mov.b64 %0,{%1,%2};" : "=l"(r) : "f"(x), "f"(y)); return r;
}
__device__ __forceinline__ void unpack2(ull v, float& x, float& y) {
    asm("mov.b64 {%0,%1},%2;" : "=f"(x), "=f"(y) : "l"(v));
}
__device__ __forceinline__ void fma2(ull& d, ull a, ull b) {
    asm("fma.rn.f32x2 %0,%1,%2,%0;" : "+l"(d) : "l"(a), "l"(b));
}
__device__ __forceinline__ float sigf(float x) { return 1.f / (1.f + expf(-x)); }

// ---------- one 18x96 @ 96x96 column pass (this thread owns column c) ----------
// Z transposed in smem: ZT[k][r], row-stride 18 (rows 0..16 real, 17 pad).
__device__ __forceinline__ void gemm_pass(const float* Zin, float* Zout,
                                          const float* __restrict__ W,
                                          const float* __restrict__ bias, int c)
{
    ull acc[9];
#pragma unroll
    for (int p = 0; p < 9; p++) acc[p] = 0ull;

    for (int k0 = 0; k0 < 96; k0 += 16) {
        float wreg[16];
#pragma unroll
        for (int u = 0; u < 16; u++) wreg[u] = __ldg(W + (k0 + u) * 96 + c);
#pragma unroll
        for (int u = 0; u < 16; u++) {
            ull w2 = pack2(wreg[u], wreg[u]);
            const ull* zp = (const ull*)(Zin + (k0 + u) * 18);
#pragma unroll
            for (int p = 0; p < 9; p++) fma2(acc[p], zp[p], w2);
        }
    }
    float bv = __ldg(bias + c);
#pragma unroll
    for (int p = 0; p < 9; p++) {
        float x, y; unpack2(acc[p], x, y);
        x = fmaxf(x + bv, 0.f); y = fmaxf(y + bv, 0.f);
        *(ull*)(Zout + c * 18 + 2 * p) = pack2(x, y);
    }
}

// last msg layer: no relu, sum over the 17 real rows
__device__ __forceinline__ void gemm_pass_sum(const float* Zin, float* msg,
                                              const float* __restrict__ W,
                                              const float* __restrict__ bias, int c)
{
    ull acc[9];
#pragma unroll
    for (int p = 0; p < 9; p++) acc[p] = 0ull;

    for (int k0 = 0; k0 < 96; k0 += 16) {
        float wreg[16];
#pragma unroll
        for (int u = 0; u < 16; u++) wreg[u] = __ldg(W + (k0 + u) * 96 + c);
#pragma unroll
        for (int u = 0; u < 16; u++) {
            ull w2 = pack2(wreg[u], wreg[u]);
            const ull* zp = (const ull*)(Zin + (k0 + u) * 18);
#pragma unroll
            for (int p = 0; p < 9; p++) fma2(acc[p], zp[p], w2);
        }
    }
    float bv = __ldg(bias + c);
    float s = 17.f * bv;
#pragma unroll
    for (int p = 0; p < 9; p++) {
        float x, y; unpack2(acc[p], x, y);
        s += x;
        if (p < 8) s += y;   // p==8 second element is pad row 17
    }
    msg[c] = s;
}

// ---------- per-step kernel: CTA == node, 96 threads (thread == column) ----------
__global__ void __launch_bounds__(96) step_kernel(
    int step,
    const int* __restrict__ edges, const int* __restrict__ target,
    const float* __restrict__ msg0_W, const float* __restrict__ msg0_b,
    const float* __restrict__ msg_Ws, const float* __restrict__ msg_bs,
    const float* __restrict__ W_ih, const float* __restrict__ W_hh,
    const float* __restrict__ pred_W, const float* __restrict__ pred_b,
    float* __restrict__ d_out)
{
    __shared__ float ZTa[96 * 18];
    __shared__ float ZTb[96 * 18];
    __shared__ float msg_s[96];
    __shared__ float gate_s[384];
    __shared__ float h2_s[96];
    __shared__ float sQ[96];
    __shared__ int   sedge[17];

    const int tid = threadIdx.x;
    const int n = blockIdx.x;
    const int j = n & 63;

    const float* Pin  = g_P[step & 1];
    float*       Pout = g_P[(step + 1) & 1];

    if (tid < 17) sedge[tid] = (n & ~63) + __ldg(edges + j * 17 + tid);
    sQ[tid] = g_Q[n * 96 + tid];
    __syncthreads();

    // ---- Z0 = relu(P[edge] + Q[self]), transposed into ZTa ----
    {
        float q = sQ[tid];
        float v[17];
#pragma unroll
        for (int r = 0; r < 17; r++)
            v[r] = __ldg(Pin + sedge[r] * 96 + tid);
#pragma unroll
        for (int r = 0; r < 17; r++)
            ZTa[tid * 18 + r] = fmaxf(v[r] + q, 0.f);
        ZTa[tid * 18 + 17] = 0.f;
    }
    __syncthreads();

    // ---- 3 message layers (each thread owns one column) ----
    gemm_pass(ZTa, ZTb, msg_Ws, msg_bs, tid);               __syncthreads();
    gemm_pass(ZTb, ZTa, msg_Ws + 9216, msg_bs + 96, tid);   __syncthreads();
    gemm_pass_sum(ZTa, msg_s, msg_Ws + 18432, msg_bs + 192, tid); __syncthreads();

    // ---- gates = msg @ W_ih[:96] + Xc + Ghh  (192 column-pairs / 96 threads) ----
#pragma unroll
    for (int q = 0; q < 2; q++) {
        int pi = tid + 96 * q;
        ull acc = 0ull;
        for (int k0 = 0; k0 < 96; k0 += 16) {
            ull wreg[16];
#pragma unroll
            for (int u = 0; u < 16; u++)
                wreg[u] = __ldg((const ull*)(W_ih + (k0 + u) * 384 + 2 * pi));
#pragma unroll
            for (int u = 0; u < 16; u++) {
                float mk = msg_s[k0 + u];
                fma2(acc, pack2(mk, mk), wreg[u]);
            }
        }
        float x, y; unpack2(acc, x, y);
        const float* xc = g_Xc  + n * 384 + 2 * pi;
        const float* gh = g_Ghh + n * 384 + 2 * pi;
        gate_s[2 * pi]     = x + xc[0] + gh[0];
        gate_s[2 * pi + 1] = y + xc[1] + gh[1];
    }
    __syncthreads();

    // ---- LSTM (one dim per thread) ----
    {
        float gi = gate_s[tid], gf = gate_s[96 + tid], gg = gate_s[192 + tid], go = gate_s[288 + tid];
        float sp = g_s[n * 96 + tid];
        float s2 = sigf(gf) * sp + sigf(gi) * tanhf(gg);
        float h2 = sigf(go) * tanhf(s2);
        g_s[n * 96 + tid] = s2;
        h2_s[tid] = h2;
    }
    __syncthreads();

    // ---- tail: P / Q / Ghh for next step ----
    if (step < NSTEP - 1) {
        // P pairs 0..47 on threads 0..47, Q pairs 0..47 on threads 48..95
        {
            int isQ = (tid >= 48);
            int pi = isQ ? (tid - 48) : tid;
            const float* Wp = msg0_W + (isQ ? 96 * 96 : 0);
            ull acc = 0ull;
            for (int k0 = 0; k0 < 96; k0 += 16) {
                ull wreg[16];
#pragma unroll
                for (int u = 0; u < 16; u++)
                    wreg[u] = __ldg((const ull*)(Wp + (k0 + u) * 96 + 2 * pi));
#pragma unroll
                for (int u = 0; u < 16; u++) {
                    float hk = h2_s[k0 + u];
                    fma2(acc, pack2(hk, hk), wreg[u]);
                }
            }
            if (isQ) {
                float x, y; unpack2(acc, x, y);
                x += __ldg(msg0_b + 2 * pi);
                y += __ldg(msg0_b + 2 * pi + 1);
                *(ull*)(g_Q + n * 96 + 2 * pi) = pack2(x, y);
            } else {
                *(ull*)(Pout + n * 96 + 2 * pi) = acc;
            }
        }
        // Ghh: 192 pairs / 96 threads
#pragma unroll
        for (int q = 0; q < 2; q++) {
            int pi = tid + 96 * q;
            ull acc = 0ull;
            for (int k0 = 0; k0 < 96; k0 += 16) {
                ull wreg[16];
#pragma unroll
                for (int u = 0; u < 16; u++)
                    wreg[u] = __ldg((const ull*)(W_hh + (k0 + u) * 384 + 2 * pi));
#pragma unroll
                for (int u = 0; u < 16; u++) {
                    float hk = h2_s[k0 + u];
                    fma2(acc, pack2(hk, hk), wreg[u]);
                }
            }
            *(ull*)(g_Ghh + n * 384 + 2 * pi) = acc;
        }
    }

    // ---- prediction head (warp 0, lanes 0..7) ----
    if (tid < 8) {
        float logit = __ldg(pred_b + tid);
#pragma unroll 8
        for (int k = 0; k < 96; k++)
            logit = fmaf(h2_s[k], __ldg(pred_W + k * 8 + tid), logit);
        const unsigned msk = 0xFFu;
        float m = logit;
        for (int off = 4; off; off >>= 1) m = fmaxf(m, __shfl_xor_sync(msk, m, off));
        float se = expf(logit - m);
        for (int off = 4; off; off >>= 1) se += __shfl_xor_sync(msk, se, off);
        float lse = m + logf(se);
        float bl = logit; int bc = tid;
        for (int off = 4; off; off >>= 1) {
            float ol = __shfl_xor_sync(msk, bl, off);
            int   oc = __shfl_xor_sync(msk, bc, off);
            if (ol > bl || (ol == bl && oc < bc)) { bl = ol; bc = oc; }
        }
        int tgt = __ldg(target + n) - 1;
        if (tid == tgt) g_nodeloss[step * 1024 + n] = lse - logit;
        if (tid == 0) {
            g_nodeok[step * 1024 + n] = (bc == tgt) ? 1 : 0;
            if (step == NSTEP - 1) d_out[33 + n] = (float)bc;
        }
    }
}

// ---------- prologue: feat -> xin MLP -> Xc; init P/Q/Ghh/s ----------
__global__ void __launch_bounds__(128) prologue_kernel(
    const int* __restrict__ x,
    const float* __restrict__ digit_emb, const float* __restrict__ row_emb,
    const float* __restrict__ col_emb,
    const float* __restrict__ in0_W, const float* __restrict__ in0_b,
    const float* __restrict__ in_Ws, const float* __restrict__ in_bs,
    const float* __restrict__ W_ih, const float* __restrict__ b_ih,
    const float* __restrict__ b_hh, const float* __restrict__ msg0_b)
{
    __shared__ float feat[4][48], va[4][96], vb[4][96];
    int tid = threadIdx.x, lane = tid & 31, w = tid >> 5;
    int n = blockIdx.x * 4 + w;
    int j = n & 63;

    if (lane < 16) {
        int xv = x[n];
        feat[w][lane]      = digit_emb[xv * 16 + lane];
        feat[w][16 + lane] = row_emb[(j >> 3) * 16 + lane];
        feat[w][32 + lane] = col_emb[(j & 7) * 16 + lane];
    }
    __syncwarp();

#pragma unroll
    for (int a = 0; a < 3; a++) {
        int c = lane + 32 * a;
        float acc = in0_b[c];
        for (int k = 0; k < 48; k++) acc = fmaf(feat[w][k], in0_W[k * 96 + c], acc);
        va[w][c] = fmaxf(acc, 0.f);
    }
    __syncwarp();

    for (int l = 0; l < 3; l++) {
        const float* Wl = in_Ws + l * 9216;
        const float* bl = in_bs + l * 96;
        float* src = (l == 1) ? vb[w] : va[w];
        float* dst = (l == 1) ? va[w] : vb[w];
#pragma unroll
        for (int a = 0; a < 3; a++) {
            int c = lane + 32 * a;
            float acc = bl[c];
            for (int k = 0; k < 96; k++) acc = fmaf(src[k], Wl[k * 96 + c], acc);
            dst[c] = (l < 2) ? fmaxf(acc, 0.f) : acc;
        }
        __syncwarp();
    }

    for (int pi = lane; pi < 192; pi += 32) {
        ull acc = 0ull;
#pragma unroll 4
        for (int k = 0; k < 96; k++) {
            ull w2 = __ldg((const ull*)(W_ih + (96 + k) * 384 + 2 * pi));
            float xk = vb[w][k];
            fma2(acc, pack2(xk, xk), w2);
        }
        float xx, yy; unpack2(acc, xx, yy);
        g_Xc[n * 384 + 2 * pi]     = xx + b_ih[2 * pi]     + b_hh[2 * pi];
        g_Xc[n * 384 + 2 * pi + 1] = yy + b_ih[2 * pi + 1] + b_hh[2 * pi + 1];
    }

    for (int t = lane; t < 96; t += 32) {
        g_P[0][n * 96 + t] = 0.f;
        g_Q[n * 96 + t]    = msg0_b[t];
        g_s[n * 96 + t]    = 0.f;
    }
    for (int t = lane; t < 384; t += 32) g_Ghh[n * 384 + t] = 0.f;
}

// ---------- epilogue: reduce loss + per-step accuracy ----------
__global__ void __launch_bounds__(512) epilogue_kernel(float* __restrict__ d_out)
{
    __shared__ int   cnt[32];
    __shared__ float red[512];
    int tid = threadIdx.x;
    if (tid < 32) cnt[tid] = 0;
    __syncthreads();

    int s = tid >> 4, b = tid & 15;
    int ok = 1;
    for (int jj = 0; jj < 64; jj++) ok &= g_nodeok[s * 1024 + b * 64 + jj];
    atomicAdd(&cnt[s], ok);

    float ls = 0.f;
    for (int i = tid; i < NSTEP * 1024; i += 512) ls += g_nodeloss[i];
    red[tid] = ls;
    __syncthreads();
    for (int off = 256; off; off >>= 1) {
        if (tid < off) red[tid] += red[tid + off];
        __syncthreads();
    }
    if (tid == 0)  d_out[0] = red[0] / (1024.f * 32.f);
    if (tid < 32)  d_out[1 + tid] = cnt[tid] * (1.f / 16.f);
}

// ---------- launch ----------
extern "C" void kernel_launch(void* const* d_in, const int* in_sizes, int n_in,
                              void* d_out, int out_size)
{
    (void)in_sizes; (void)n_in; (void)out_size;
    const int*   x         = (const int*)  d_in[0];
    const int*   target    = (const int*)  d_in[1];
    const int*   edges     = (const int*)  d_in[2];
    const float* digit_emb = (const float*)d_in[3];
    const float* row_emb   = (const float*)d_in[4];
    const float* col_emb   = (const float*)d_in[5];
    const float* in0_W     = (const float*)d_in[6];
    const float* in0_b     = (const float*)d_in[7];
    const float* in_Ws     = (const float*)d_in[8];
    const float* in_bs     = (const float*)d_in[9];
    const float* msg0_W    = (const float*)d_in[10];
    const float* msg0_b    = (const float*)d_in[11];
    const float* msg_Ws    = (const float*)d_in[12];
    const float* msg_bs    = (const float*)d_in[13];
    const float* W_ih      = (const float*)d_in[14];
    const float* W_hh      = (const float*)d_in[15];
    const float* b_ih      = (const float*)d_in[16];
    const float* b_hh      = (const float*)d_in[17];
    const float* pred_W    = (const float*)d_in[18];
    const float* pred_b    = (const float*)d_in[19];
    float* out = (float*)d_out;

    prologue_kernel<<<256, 128>>>(x, digit_emb, row_emb, col_emb,
                                  in0_W, in0_b, in_Ws, in_bs,
                                  W_ih, b_ih, b_hh, msg0_b);
    for (int s = 0; s < NSTEP; s++)
        step_kernel<<<1024, 96>>>(s, edges, target,
                                  msg0_W, msg0_b, msg_Ws, msg_bs,
                                  W_ih, W_hh, pred_W, pred_b, out);
    epilogue_kernel<<<1, 512>>>(out);
}